// round 9
// baseline (speedup 1.0000x reference)
#include <cuda_runtime.h>
#include <cuda_bf16.h>
#include <math.h>
#include <stdint.h>

#define H   1024
#define NH  16
#define HD  64
#define BSZ 2
#define SEQ 2048
#define MTOT (BSZ*SEQ)   // 4096 rows

// 0.125 (1/sqrt(HD)) * log2(e): folded into Q projection
#define QSCALE 0.18033688011112042f

// ---------------------------------------------------------------------------
// Scratch (allocation-free rule: __device__ globals)
// ---------------------------------------------------------------------------
__device__ __nv_bfloat16 g_Qhi[MTOT * H];
__device__ __nv_bfloat16 g_Qlo[MTOT * H];
__device__ __nv_bfloat16 g_Khi[MTOT * H];
__device__ __nv_bfloat16 g_Klo[MTOT * H];
__device__ __nv_bfloat16 g_Vhi[MTOT * H];
__device__ __nv_bfloat16 g_Vlo[MTOT * H];
__device__ __nv_bfloat16 g_chi[MTOT * H];
__device__ __nv_bfloat16 g_clo[MTOT * H];
__device__ __nv_bfloat16 g_xhi[MTOT * H];
__device__ __nv_bfloat16 g_xlo[MTOT * H];
__device__ __nv_bfloat16 g_WThi[4][H * H];   // W^T (q,k,v,o contiguous), bf16-hi
__device__ __nv_bfloat16 g_WTlo[4][H * H];   // W^T, bf16-lo

// ---------------------------------------------------------------------------
// helpers
// ---------------------------------------------------------------------------
__device__ __forceinline__ uint32_t smem_u32(const void* p) {
    uint32_t a;
    asm("{ .reg .u64 t; cvta.to.shared.u64 t, %1; cvt.u32.u64 %0, t; }"
        : "=r"(a) : "l"(p));
    return a;
}
__device__ __forceinline__ void ldsm_x4(uint32_t* r, uint32_t addr) {
    asm volatile("ldmatrix.sync.aligned.m8n8.x4.shared.b16 {%0,%1,%2,%3}, [%4];"
                 : "=r"(r[0]), "=r"(r[1]), "=r"(r[2]), "=r"(r[3]) : "r"(addr));
}
__device__ __forceinline__ void ldsm_x4t(uint32_t* r, uint32_t addr) {
    asm volatile("ldmatrix.sync.aligned.m8n8.x4.trans.shared.b16 {%0,%1,%2,%3}, [%4];"
                 : "=r"(r[0]), "=r"(r[1]), "=r"(r[2]), "=r"(r[3]) : "r"(addr));
}
__device__ __forceinline__ void mma_bf16(float* c, const uint32_t* a,
                                         const uint32_t* b) {
    asm volatile(
        "mma.sync.aligned.m16n8k16.row.col.f32.bf16.bf16.f32 "
        "{%0,%1,%2,%3}, {%4,%5,%6,%7}, {%8,%9}, {%0,%1,%2,%3};"
        : "+f"(c[0]), "+f"(c[1]), "+f"(c[2]), "+f"(c[3])
        : "r"(a[0]), "r"(a[1]), "r"(a[2]), "r"(a[3]), "r"(b[0]), "r"(b[1]));
}
__device__ __forceinline__ float exp2a(float x) {
    float y;
    asm("ex2.approx.f32 %0, %1;" : "=f"(y) : "f"(x));
    return y;
}
__device__ __forceinline__ void split2(float a, float b, uint32_t& hi, uint32_t& lo) {
    __nv_bfloat162 h = __floats2bfloat162_rn(a, b);
    float ra = a - __bfloat162float(h.x);
    float rb = b - __bfloat162float(h.y);
    __nv_bfloat162 l = __floats2bfloat162_rn(ra, rb);
    hi = *(uint32_t*)&h;
    lo = *(uint32_t*)&l;
}
__device__ __forceinline__ void cp16(uint32_t saddr, const void* g) {
    asm volatile("cp.async.cg.shared.global [%0], [%1], 16;"
                 :: "r"(saddr), "l"(g) : "memory");
}
__device__ __forceinline__ void cp_commit() {
    asm volatile("cp.async.commit_group;" ::: "memory");
}
template <int N>
__device__ __forceinline__ void cp_wait() {
    asm volatile("cp.async.wait_group %0;" :: "n"(N) : "memory");
}

// ---------------------------------------------------------------------------
// Prep
// ---------------------------------------------------------------------------
__global__ __launch_bounds__(256) void split_bf16_v4(
    const float* __restrict__ src, __nv_bfloat16* __restrict__ hi,
    __nv_bfloat16* __restrict__ lo, int n4)
{
    int i = blockIdx.x * 256 + threadIdx.x;
    if (i < n4) {
        float4 v = ((const float4*)src)[i];
        __nv_bfloat162 h0 = __floats2bfloat162_rn(v.x, v.y);
        __nv_bfloat162 h1 = __floats2bfloat162_rn(v.z, v.w);
        __nv_bfloat162 l0 = __floats2bfloat162_rn(v.x - __bfloat162float(h0.x),
                                                  v.y - __bfloat162float(h0.y));
        __nv_bfloat162 l1 = __floats2bfloat162_rn(v.z - __bfloat162float(h1.x),
                                                  v.w - __bfloat162float(h1.y));
        uint2 ho = { *(uint32_t*)&h0, *(uint32_t*)&h1 };
        uint2 loo = { *(uint32_t*)&l0, *(uint32_t*)&l1 };
        ((uint2*)hi)[i] = ho;
        ((uint2*)lo)[i] = loo;
    }
}

__global__ __launch_bounds__(256) void transpose_split4(
    const float* __restrict__ W0, const float* __restrict__ W1,
    const float* __restrict__ W2, const float* __restrict__ W3,
    __nv_bfloat16* __restrict__ hi, __nv_bfloat16* __restrict__ lo)
{
    __shared__ float t[32][33];
    const int z = blockIdx.z;
    const float* W = (z == 0) ? W0 : (z == 1) ? W1 : (z == 2) ? W2 : W3;
    const size_t off = (size_t)z * H * H;
    const int tx = threadIdx.x, ty = threadIdx.y;   // (32, 8)
    const int bx = blockIdx.x, by = blockIdx.y;
    #pragma unroll
    for (int i = 0; i < 4; i++)
        t[ty + 8 * i][tx] = W[(size_t)(by * 32 + ty + 8 * i) * H + bx * 32 + tx];
    __syncthreads();
    #pragma unroll
    for (int i = 0; i < 4; i++) {
        float v = t[tx][ty + 8 * i];
        int n = bx * 32 + ty + 8 * i;
        int k = by * 32 + tx;
        __nv_bfloat16 h = __float2bfloat16(v);
        hi[off + (size_t)n * H + k] = h;
        lo[off + (size_t)n * H + k] = __float2bfloat16(v - __bfloat162float(h));
    }
}

// ---------------------------------------------------------------------------
// HMMA split-bf16 GEMM mainloop: 128x128 CTA tile, BK=32, 8 warps (2x4),
// 2-stage cp.async, one barrier per iter, x4 B loads, product-outer MMAs.
// ---------------------------------------------------------------------------
#define ROWB 80
#define TILEB (128 * ROWB)            // 10240
#define STAGEB (4 * TILEB)            // 40960
#define GEMM_SMEM (2 * STAGEB)        // 81920

__device__ __forceinline__ void gemm_mainloop(
    const __nv_bfloat16* __restrict__ Ahi, const __nv_bfloat16* __restrict__ Alo,
    const __nv_bfloat16* __restrict__ Bhi, const __nv_bfloat16* __restrict__ Blo,
    int m0, uint32_t sb, float acc[4][4][4])
{
    const int tid  = threadIdx.x;
    const int wid  = tid >> 5;
    const int lane = tid & 31;
    const int warp_m = wid >> 2;
    const int warp_n = wid & 3;

    const uint32_t a_row = (lane & 15);
    const uint32_t a_koff = (lane >> 4) * 16;
    const uint32_t b_row16 = (lane & 7) + ((lane >> 4) & 1) * 8;
    const uint32_t b_koff = ((lane >> 3) & 1) * 16;

    const int g_row0 = tid >> 2;
    const int g_u4   = tid & 3;

    auto load_stage = [&](int stage, int k0) {
        const uint32_t st = sb + stage * STAGEB;
        #pragma unroll
        for (int i = 0; i < 2; i++) {
            const int row = g_row0 + i * 64;
            const uint32_t so = (uint32_t)row * ROWB + g_u4 * 16;
            const size_t ga = (size_t)(m0 + row) * H + k0 + g_u4 * 8;
            const size_t gb = (size_t)row * H + k0 + g_u4 * 8;
            cp16(st + 0 * TILEB + so, Ahi + ga);
            cp16(st + 1 * TILEB + so, Alo + ga);
            cp16(st + 2 * TILEB + so, Bhi + gb);
            cp16(st + 3 * TILEB + so, Blo + gb);
        }
        cp_commit();
    };

    load_stage(0, 0);

    for (int kc = 0; kc < 32; kc++) {
        cp_wait<0>();
        __syncthreads();
        if (kc < 31) load_stage((kc + 1) & 1, (kc + 1) * 32);

        const uint32_t st = sb + (kc & 1) * STAGEB;
        const uint32_t S_AHI = st, S_ALO = st + TILEB,
                       S_BHI = st + 2 * TILEB, S_BLO = st + 3 * TILEB;

        #pragma unroll
        for (int ks = 0; ks < 2; ks++) {
            const uint32_t kb = ks * 32;
            uint32_t bh[4][2], bl[4][2];
            #pragma unroll
            for (int nfp = 0; nfp < 2; nfp++) {
                const uint32_t boff =
                    (uint32_t)(warp_n * 32 + nfp * 16 + b_row16) * ROWB + kb + b_koff;
                ldsm_x4(&bh[2 * nfp][0], S_BHI + boff);
                ldsm_x4(&bl[2 * nfp][0], S_BLO + boff);
            }
            #pragma unroll
            for (int mf = 0; mf < 4; mf++) {
                const uint32_t aoff =
                    (uint32_t)(warp_m * 64 + mf * 16 + a_row) * ROWB + kb + a_koff;
                uint32_t ah[4], al[4];
                ldsm_x4(ah, S_AHI + aoff);
                ldsm_x4(al, S_ALO + aoff);
                #pragma unroll
                for (int nf = 0; nf < 4; nf++) mma_bf16(acc[mf][nf], ah, bh[nf]);
                #pragma unroll
                for (int nf = 0; nf < 4; nf++) mma_bf16(acc[mf][nf], ah, bl[nf]);
                #pragma unroll
                for (int nf = 0; nf < 4; nf++) mma_bf16(acc[mf][nf], al, bh[nf]);
            }
        }
    }
}

// Fused QKV projection: B = concatenated [3072 x 1024] W^T.
__global__ __launch_bounds__(256, 2) void gemm_qkv(
    const __nv_bfloat16* __restrict__ Ahi, const __nv_bfloat16* __restrict__ Alo,
    const __nv_bfloat16* __restrict__ WThi, const __nv_bfloat16* __restrict__ WTlo,
    const float* __restrict__ bq, const float* __restrict__ bk,
    const float* __restrict__ bv,
    __nv_bfloat16* __restrict__ Qhi, __nv_bfloat16* __restrict__ Qlo,
    __nv_bfloat16* __restrict__ Khi, __nv_bfloat16* __restrict__ Klo,
    __nv_bfloat16* __restrict__ Vhi, __nv_bfloat16* __restrict__ Vlo)
{
    extern __shared__ __align__(16) char smem[];
    const uint32_t sb = smem_u32(smem);
    const int m0 = blockIdx.y * 128;
    const int n0 = blockIdx.x * 128;   // 0..2944

    float acc[4][4][4];
    #pragma unroll
    for (int i = 0; i < 4; i++)
        #pragma unroll
        for (int j = 0; j < 4; j++)
            #pragma unroll
            for (int r = 0; r < 4; r++) acc[i][j][r] = 0.0f;

    gemm_mainloop(Ahi, Alo, WThi + (size_t)n0 * H, WTlo + (size_t)n0 * H,
                  m0, sb, acc);

    const int sec = n0 >> 10;
    const float* bias = (sec == 0) ? bq : (sec == 1) ? bk : bv;
    const float scale = (sec == 0) ? QSCALE : 1.0f;
    __nv_bfloat16* Chi = (sec == 0) ? Qhi : (sec == 1) ? Khi : Vhi;
    __nv_bfloat16* Clo = (sec == 0) ? Qlo : (sec == 1) ? Klo : Vlo;
    const int nloc0 = n0 & 1023;

    const int tid  = threadIdx.x;
    const int wid  = tid >> 5;
    const int lane = tid & 31;
    const int warp_m = wid >> 2;
    const int warp_n = wid & 3;
    const int r_in = lane >> 2;
    const int c_in = (lane & 3) * 2;
    #pragma unroll
    for (int nf = 0; nf < 4; nf++) {
        const int col = nloc0 + warp_n * 32 + nf * 8 + c_in;
        const float2 bv2 = *(const float2*)(bias + col);
        #pragma unroll
        for (int mf = 0; mf < 4; mf++) {
            const int row = m0 + warp_m * 64 + mf * 16 + r_in;
            float v00 = (acc[mf][nf][0] + bv2.x) * scale;
            float v01 = (acc[mf][nf][1] + bv2.y) * scale;
            float v10 = (acc[mf][nf][2] + bv2.x) * scale;
            float v11 = (acc[mf][nf][3] + bv2.y) * scale;
            uint32_t h0, l0, h1, l1;
            split2(v00, v01, h0, l0);
            split2(v10, v11, h1, l1);
            *(uint32_t*)(Chi + (size_t)row * H + col) = h0;
            *(uint32_t*)(Clo + (size_t)row * H + col) = l0;
            *(uint32_t*)(Chi + (size_t)(row + 8) * H + col) = h1;
            *(uint32_t*)(Clo + (size_t)(row + 8) * H + col) = l1;
        }
    }
}

// Output projection: f32 out
__global__ __launch_bounds__(256, 2) void gemm_o(
    const __nv_bfloat16* __restrict__ Ahi, const __nv_bfloat16* __restrict__ Alo,
    const __nv_bfloat16* __restrict__ WThi, const __nv_bfloat16* __restrict__ WTlo,
    const float* __restrict__ bias, float* __restrict__ C)
{
    extern __shared__ __align__(16) char smem[];
    const uint32_t sb = smem_u32(smem);
    const int m0 = blockIdx.y * 128;
    const int n0 = blockIdx.x * 128;

    float acc[4][4][4];
    #pragma unroll
    for (int i = 0; i < 4; i++)
        #pragma unroll
        for (int j = 0; j < 4; j++)
            #pragma unroll
            for (int r = 0; r < 4; r++) acc[i][j][r] = 0.0f;

    gemm_mainloop(Ahi, Alo, WThi + (size_t)n0 * H, WTlo + (size_t)n0 * H,
                  m0, sb, acc);

    const int tid  = threadIdx.x;
    const int wid  = tid >> 5;
    const int lane = tid & 31;
    const int warp_m = wid >> 2;
    const int warp_n = wid & 3;
    const int r_in = lane >> 2;
    const int c_in = (lane & 3) * 2;
    #pragma unroll
    for (int nf = 0; nf < 4; nf++) {
        const int col = n0 + warp_n * 32 + nf * 8 + c_in;
        const float2 bv2 = *(const float2*)(bias + col);
        #pragma unroll
        for (int mf = 0; mf < 4; mf++) {
            const int row = m0 + warp_m * 64 + mf * 16 + r_in;
            float2 o0 = { acc[mf][nf][0] + bv2.x, acc[mf][nf][1] + bv2.y };
            float2 o1 = { acc[mf][nf][2] + bv2.x, acc[mf][nf][3] + bv2.y };
            *(float2*)(C + (size_t)row * H + col) = o0;
            *(float2*)(C + (size_t)(row + 8) * H + col) = o1;
        }
    }
}

// ---------------------------------------------------------------------------
// HMMA flash attention, Br=128 (8 warps, 256 thr), Bc=64 KV tiles,
// 2-stage cp.async, one barrier/iter. 110.6KB smem -> 2 CTAs/SM (16 warps).
// grid (SEQ/128, BSZ*NH). Warp w owns q rows qb*128 + w*16 .. +15.
// ---------------------------------------------------------------------------
#define AROW 144
#define QROWS 128
#define QTILE (QROWS * AROW)           // 18432
#define KVTILE (64 * AROW)             // 9216
#define KVSTAGE (4 * KVTILE)           // 36864
#define ATTN_SMEM (2 * QTILE + 2 * KVSTAGE)   // 110592

__global__ __launch_bounds__(256, 2) void attn_hmma(
    const __nv_bfloat16* __restrict__ Qhi, const __nv_bfloat16* __restrict__ Qlo,
    const __nv_bfloat16* __restrict__ Khi, const __nv_bfloat16* __restrict__ Klo,
    const __nv_bfloat16* __restrict__ Vhi, const __nv_bfloat16* __restrict__ Vlo,
    __nv_bfloat16* __restrict__ Chi, __nv_bfloat16* __restrict__ Clo)
{
    extern __shared__ __align__(16) char smem[];
    const uint32_t sb = smem_u32(smem);
    const uint32_t S_QH = 0, S_QL = QTILE;

    const int tid  = threadIdx.x;
    const int warp = tid >> 5;
    const int lane = tid & 31;
    const int qb = blockIdx.x;
    const int b  = blockIdx.y / NH;
    const int h  = blockIdx.y % NH;
    const size_t hcol = (size_t)h * HD;
    const size_t rbase = (size_t)b * SEQ;

    // Q tile (128 x 64 bf16, hi+lo)
    #pragma unroll
    for (int t = 0; t < 4; t++) {
        const int idx = tid + t * 256;          // 0..1023
        const int r = idx >> 3, c = idx & 7;
        const uint32_t so = (uint32_t)r * AROW + c * 16;
        const size_t g = (rbase + qb * 128 + r) * H + hcol + c * 8;
        cp16(sb + S_QH + so, Qhi + g);
        cp16(sb + S_QL + so, Qlo + g);
    }
    cp_commit();

    auto load_kv = [&](int stage, int kb) {
        const uint32_t st = sb + 2 * QTILE + stage * KVSTAGE;
        #pragma unroll
        for (int t = 0; t < 2; t++) {
            const int idx = tid + t * 256;      // 0..511
            const int r = idx >> 3, c = idx & 7;
            const uint32_t so = (uint32_t)r * AROW + c * 16;
            const size_t g = (rbase + kb * 64 + r) * H + hcol + c * 8;
            cp16(st + 0 * KVTILE + so, Khi + g);
            cp16(st + 1 * KVTILE + so, Klo + g);
            cp16(st + 2 * KVTILE + so, Vhi + g);
            cp16(st + 3 * KVTILE + so, Vlo + g);
        }
        cp_commit();
    };

    float O[8][4];
    #pragma unroll
    for (int d = 0; d < 8; d++)
        #pragma unroll
        for (int r = 0; r < 4; r++) O[d][r] = 0.0f;
    float m0 = -1e30f, m1 = -1e30f, l0 = 0.0f, l1 = 0.0f;

    const uint32_t a_base = S_QH + (uint32_t)(warp * 16 + (lane & 15)) * AROW
                          + (lane >> 4) * 16;
    const uint32_t al_base = a_base + QTILE;
    const uint32_t b_row16 = (lane & 7) + ((lane >> 4) & 1) * 8;
    const uint32_t b_koff = ((lane >> 3) & 1) * 16;

    const int r_in = lane >> 2;
    const int c_in = (lane & 3) * 2;

    const int nkb = 2 * qb + 2;
    load_kv(0, 0);

    for (int kb = 0; kb < nkb; kb++) {
        cp_wait<0>();
        __syncthreads();
        if (kb + 1 < nkb) load_kv((kb + 1) & 1, kb + 1);

        const uint32_t st = sb + 2 * QTILE + (kb & 1) * KVSTAGE;
        const uint32_t S_KH = st, S_KL = st + KVTILE,
                       S_VH = st + 2 * KVTILE, S_VL = st + 3 * KVTILE;

        float s[8][4];
        #pragma unroll
        for (int nf = 0; nf < 8; nf++)
            #pragma unroll
            for (int r = 0; r < 4; r++) s[nf][r] = 0.0f;

        // S = Q K^T; single reusable K-frag buffer keeps regs low:
        //   load K-hi -> (qh*kh, ql*kh), overwrite with K-lo -> (qh*kl)
        #pragma unroll
        for (int ks = 0; ks < 4; ks++) {
            uint32_t ah[4], al[4], bb[8][2];
            ldsm_x4(ah, sb + a_base + ks * 32);
            ldsm_x4(al, sb + al_base + ks * 32);
            #pragma unroll
            for (int nfp = 0; nfp < 4; nfp++) {
                const uint32_t bo =
                    (uint32_t)(nfp * 16 + b_row16) * AROW + ks * 32 + b_koff;
                ldsm_x4(&bb[2 * nfp][0], S_KH + bo);
            }
            #pragma unroll
            for (int nf = 0; nf < 8; nf++) mma_bf16(s[nf], ah, bb[nf]);
            #pragma unroll
            for (int nf = 0; nf < 8; nf++) mma_bf16(s[nf], al, bb[nf]);
            #pragma unroll
            for (int nfp = 0; nfp < 4; nfp++) {
                const uint32_t bo =
                    (uint32_t)(nfp * 16 + b_row16) * AROW + ks * 32 + b_koff;
                ldsm_x4(&bb[2 * nfp][0], S_KL + bo);
            }
            #pragma unroll
            for (int nf = 0; nf < 8; nf++) mma_bf16(s[nf], ah, bb[nf]);
        }

        if (kb >= 2 * qb) {   // tiles overlapping the diagonal
            const int row0 = qb * 128 + warp * 16 + r_in;
            const int row1 = row0 + 8;
            #pragma unroll
            for (int nf = 0; nf < 8; nf++) {
                const int cg = kb * 64 + nf * 8 + c_in;
                if (cg > row0)     s[nf][0] = -1e30f;
                if (cg + 1 > row0) s[nf][1] = -1e30f;
                if (cg > row1)     s[nf][2] = -1e30f;
                if (cg + 1 > row1) s[nf][3] = -1e30f;
            }
        }

        float rmax0 = -1e30f, rmax1 = -1e30f;
        #pragma unroll
        for (int nf = 0; nf < 8; nf++) {
            rmax0 = fmaxf(rmax0, fmaxf(s[nf][0], s[nf][1]));
            rmax1 = fmaxf(rmax1, fmaxf(s[nf][2], s[nf][3]));
        }
        rmax0 = fmaxf(rmax0, __shfl_xor_sync(0xffffffffu, rmax0, 1));
        rmax0 = fmaxf(rmax0, __shfl_xor_sync(0xffffffffu, rmax0, 2));
        rmax1 = fmaxf(rmax1, __shfl_xor_sync(0xffffffffu, rmax1, 1));
        rmax1 = fmaxf(rmax1, __shfl_xor_sync(0xffffffffu, rmax1, 2));
        const float mn0 = fmaxf(m0, rmax0);
        const float mn1 = fmaxf(m1, rmax1);
        const float sc0 = exp2a(m0 - mn0);
        const float sc1 = exp2a(m1 - mn1);

        float rs0 = 0.0f, rs1 = 0.0f;
        #pragma unroll
        for (int nf = 0; nf < 8; nf++) {
            s[nf][0] = exp2a(s[nf][0] - mn0);
            s[nf][1] = exp2a(s[nf][1] - mn0);
            s[nf][2] = exp2a(s[nf][2] - mn1);
            s[nf][3] = exp2a(s[nf][3] - mn1);
            rs0 += s[nf][0] + s[nf][1];
            rs1 += s[nf][2] + s[nf][3];
        }
        rs0 += __shfl_xor_sync(0xffffffffu, rs0, 1);
        rs0 += __shfl_xor_sync(0xffffffffu, rs0, 2);
        rs1 += __shfl_xor_sync(0xffffffffu, rs1, 1);
        rs1 += __shfl_xor_sync(0xffffffffu, rs1, 2);
        l0 = l0 * sc0 + rs0;
        l1 = l1 * sc1 + rs1;
        m0 = mn0; m1 = mn1;
        #pragma unroll
        for (int d = 0; d < 8; d++) {
            O[d][0] *= sc0; O[d][1] *= sc0;
            O[d][2] *= sc1; O[d][3] *= sc1;
        }

        // O += P V (P split on the fly; x4.trans V loads over 32 kv rows)
        #pragma unroll
        for (int pair = 0; pair < 2; pair++) {
            const int k0f = 4 * pair;
            uint32_t ph0[4], pl0[4], ph1[4], pl1[4];
            split2(s[k0f+0][0], s[k0f+0][1], ph0[0], pl0[0]);
            split2(s[k0f+0][2], s[k0f+0][3], ph0[1], pl0[1]);
            split2(s[k0f+1][0], s[k0f+1][1], ph0[2], pl0[2]);
            split2(s[k0f+1][2], s[k0f+1][3], ph0[3], pl0[3]);
            split2(s[k0f+2][0], s[k0f+2][1], ph1[0], pl1[0]);
            split2(s[k0f+2][2], s[k0f+2][3], ph1[1], pl1[1]);
            split2(s[k0f+3][0], s[k0f+3][1], ph1[2], pl1[2]);
            split2(s[k0f+3][2], s[k0f+3][3], ph1[3], pl1[3]);

            const uint32_t vrow = (uint32_t)(pair * 32 + lane) * AROW;
            #pragma unroll
            for (int dfp = 0; dfp < 4; dfp++) {
                const int df0 = 2 * dfp, df1 = 2 * dfp + 1;
                uint32_t vha[4], vla[4], vhb[4], vlb[4];
                ldsm_x4t(vha, S_VH + vrow + df0 * 16);
                ldsm_x4t(vla, S_VL + vrow + df0 * 16);
                ldsm_x4t(vhb, S_VH + vrow + df1 * 16);
                ldsm_x4t(vlb, S_VL + vrow + df1 * 16);
                mma_bf16(O[df0], ph0, &vha[0]);
                mma_bf16(O[df1], ph0, &vhb[0]);
                mma_bf16(O[df0], ph1, &vha[2]);
                mma_bf16(O[df1], ph1, &vhb[2]);
                mma_bf16(O[df0], ph0, &vla[0]);
                mma_bf16(O[df1], ph0, &vlb[0]);
                mma_bf16(O[df0], ph1, &vla[2]);
                mma_bf16(O[df1], ph1, &vlb[2]);
                mma_bf16(O[df0], pl0, &vha[0]);
                mma_bf16(O[df1], pl0, &vhb[0]);
                mma_bf16(O[df0], pl1, &vha[2]);
                mma_bf16(O[df1], pl1, &vhb[2]);
            }
        }
    }

    const float inv0 = 1.0f / l0;
    const float inv1 = 1.0f / l1;
    const int row0 = qb * 128 + warp * 16 + r_in;
    #pragma unroll
    for (int df = 0; df < 8; df++) {
        const size_t col = hcol + df * 8 + c_in;
        uint32_t h0, lo0, h1, lo1;
        split2(O[df][0] * inv0, O[df][1] * inv0, h0, lo0);
        split2(O[df][2] * inv1, O[df][3] * inv1, h1, lo1);
        *(uint32_t*)(Chi + (rbase + row0) * H + col) = h0;
        *(uint32_t*)(Clo + (rbase + row0) * H + col) = lo0;
        *(uint32_t*)(Chi + (rbase + row0 + 8) * H + col) = h1;
        *(uint32_t*)(Clo + (rbase + row0 + 8) * H + col) = lo1;
    }
}

// ---------------------------------------------------------------------------
extern "C" void kernel_launch(void* const* d_in, const int* in_sizes, int n_in,
                              void* d_out, int out_size)
{
    const float* x  = (const float*)d_in[0];
    const float* Wq = (const float*)d_in[1];
    const float* bq = (const float*)d_in[2];
    const float* Wk = (const float*)d_in[3];
    const float* bk = (const float*)d_in[4];
    const float* Wv = (const float*)d_in[5];
    const float* bv = (const float*)d_in[6];
    const float* Wo = (const float*)d_in[7];
    const float* bo = (const float*)d_in[8];
    float* out = (float*)d_out;

    cudaFuncSetAttribute(gemm_qkv,
                         cudaFuncAttributeMaxDynamicSharedMemorySize, GEMM_SMEM);
    cudaFuncSetAttribute(gemm_o,
                         cudaFuncAttributeMaxDynamicSharedMemorySize, GEMM_SMEM);
    cudaFuncSetAttribute(attn_hmma,
                         cudaFuncAttributeMaxDynamicSharedMemorySize, ATTN_SMEM);

    __nv_bfloat16 *qhi, *qlo, *khi, *klo, *vhi, *vlo, *chi, *clo;
    __nv_bfloat16 *xhi, *xlo, *wthi, *wtlo;
    cudaGetSymbolAddress((void**)&qhi, g_Qhi);
    cudaGetSymbolAddress((void**)&qlo, g_Qlo);
    cudaGetSymbolAddress((void**)&khi, g_Khi);
    cudaGetSymbolAddress((void**)&klo, g_Klo);
    cudaGetSymbolAddress((void**)&vhi, g_Vhi);
    cudaGetSymbolAddress((void**)&vlo, g_Vlo);
    cudaGetSymbolAddress((void**)&chi, g_chi);
    cudaGetSymbolAddress((void**)&clo, g_clo);
    cudaGetSymbolAddress((void**)&xhi, g_xhi);
    cudaGetSymbolAddress((void**)&xlo, g_xlo);
    cudaGetSymbolAddress((void**)&wthi, g_WThi);
    cudaGetSymbolAddress((void**)&wtlo, g_WTlo);

    const int nelem = MTOT * H;
    const size_t WSZ = (size_t)H * H;

    split_bf16_v4<<<(nelem / 4 + 255) / 256, 256>>>(x, xhi, xlo, nelem / 4);
    dim3 tgrid(H / 32, H / 32, 4), tblk(32, 8);
    transpose_split4<<<tgrid, tblk>>>(Wq, Wk, Wv, Wo, wthi, wtlo);

    dim3 qkvgrid(3 * H / 128, MTOT / 128);   // (24, 32)
    gemm_qkv<<<qkvgrid, 256, GEMM_SMEM>>>(xhi, xlo, wthi, wtlo,
        bq, bk, bv, qhi, qlo, khi, klo, vhi, vlo);

    dim3 agrid(SEQ / 128, BSZ * NH);         // (16, 32)
    attn_hmma<<<agrid, 256, ATTN_SMEM>>>(qhi, qlo, khi, klo, vhi, vlo, chi, clo);

    dim3 ogrid(H / 128, MTOT / 128);         // (8, 32)
    gemm_o<<<ogrid, 256, GEMM_SMEM>>>(chi, clo, wthi + 3 * WSZ, wtlo + 3 * WSZ,
                                      bo, out);
}

// round 10
// speedup vs baseline: 1.0549x; 1.0549x over previous
#include <cuda_runtime.h>
#include <cuda_bf16.h>
#include <math.h>
#include <stdint.h>

#define H   1024
#define NH  16
#define HD  64
#define BSZ 2
#define SEQ 2048
#define MTOT (BSZ*SEQ)   // 4096 rows

// 0.125 (1/sqrt(HD)) * log2(e): folded into Q projection
#define QSCALE 0.18033688011112042f

// ---------------------------------------------------------------------------
// Scratch (allocation-free rule: __device__ globals)
// ---------------------------------------------------------------------------
__device__ __nv_bfloat16 g_Qhi[MTOT * H];
__device__ __nv_bfloat16 g_Qlo[MTOT * H];
__device__ __nv_bfloat16 g_Khi[MTOT * H];
__device__ __nv_bfloat16 g_Klo[MTOT * H];
__device__ __nv_bfloat16 g_Vhi[MTOT * H];
__device__ __nv_bfloat16 g_Vlo[MTOT * H];
__device__ __nv_bfloat16 g_chi[MTOT * H];
__device__ __nv_bfloat16 g_clo[MTOT * H];
__device__ __nv_bfloat16 g_xhi[MTOT * H];
__device__ __nv_bfloat16 g_xlo[MTOT * H];
__device__ __nv_bfloat16 g_WThi[4][H * H];   // W^T (q,k,v,o contiguous), bf16-hi
__device__ __nv_bfloat16 g_WTlo[4][H * H];   // W^T, bf16-lo

// ---------------------------------------------------------------------------
// helpers
// ---------------------------------------------------------------------------
__device__ __forceinline__ uint32_t smem_u32(const void* p) {
    uint32_t a;
    asm("{ .reg .u64 t; cvta.to.shared.u64 t, %1; cvt.u32.u64 %0, t; }"
        : "=r"(a) : "l"(p));
    return a;
}
__device__ __forceinline__ void ldsm_x4(uint32_t* r, uint32_t addr) {
    asm volatile("ldmatrix.sync.aligned.m8n8.x4.shared.b16 {%0,%1,%2,%3}, [%4];"
                 : "=r"(r[0]), "=r"(r[1]), "=r"(r[2]), "=r"(r[3]) : "r"(addr));
}
__device__ __forceinline__ void ldsm_x4t(uint32_t* r, uint32_t addr) {
    asm volatile("ldmatrix.sync.aligned.m8n8.x4.trans.shared.b16 {%0,%1,%2,%3}, [%4];"
                 : "=r"(r[0]), "=r"(r[1]), "=r"(r[2]), "=r"(r[3]) : "r"(addr));
}
__device__ __forceinline__ void mma_bf16(float* c, const uint32_t* a,
                                         const uint32_t* b) {
    asm volatile(
        "mma.sync.aligned.m16n8k16.row.col.f32.bf16.bf16.f32 "
        "{%0,%1,%2,%3}, {%4,%5,%6,%7}, {%8,%9}, {%0,%1,%2,%3};"
        : "+f"(c[0]), "+f"(c[1]), "+f"(c[2]), "+f"(c[3])
        : "r"(a[0]), "r"(a[1]), "r"(a[2]), "r"(a[3]), "r"(b[0]), "r"(b[1]));
}
__device__ __forceinline__ float exp2a(float x) {
    float y;
    asm("ex2.approx.f32 %0, %1;" : "=f"(y) : "f"(x));
    return y;
}
__device__ __forceinline__ void split2(float a, float b, uint32_t& hi, uint32_t& lo) {
    __nv_bfloat162 h = __floats2bfloat162_rn(a, b);
    float ra = a - __bfloat162float(h.x);
    float rb = b - __bfloat162float(h.y);
    __nv_bfloat162 l = __floats2bfloat162_rn(ra, rb);
    hi = *(uint32_t*)&h;
    lo = *(uint32_t*)&l;
}
__device__ __forceinline__ void cp16(uint32_t saddr, const void* g) {
    asm volatile("cp.async.cg.shared.global [%0], [%1], 16;"
                 :: "r"(saddr), "l"(g) : "memory");
}
__device__ __forceinline__ void cp_commit() {
    asm volatile("cp.async.commit_group;" ::: "memory");
}
template <int N>
__device__ __forceinline__ void cp_wait() {
    asm volatile("cp.async.wait_group %0;" :: "n"(N) : "memory");
}

// ---------------------------------------------------------------------------
// Prep
// ---------------------------------------------------------------------------
__global__ __launch_bounds__(256) void split_bf16_v4(
    const float* __restrict__ src, __nv_bfloat16* __restrict__ hi,
    __nv_bfloat16* __restrict__ lo, int n4)
{
    int i = blockIdx.x * 256 + threadIdx.x;
    if (i < n4) {
        float4 v = ((const float4*)src)[i];
        __nv_bfloat162 h0 = __floats2bfloat162_rn(v.x, v.y);
        __nv_bfloat162 h1 = __floats2bfloat162_rn(v.z, v.w);
        __nv_bfloat162 l0 = __floats2bfloat162_rn(v.x - __bfloat162float(h0.x),
                                                  v.y - __bfloat162float(h0.y));
        __nv_bfloat162 l1 = __floats2bfloat162_rn(v.z - __bfloat162float(h1.x),
                                                  v.w - __bfloat162float(h1.y));
        uint2 ho = { *(uint32_t*)&h0, *(uint32_t*)&h1 };
        uint2 loo = { *(uint32_t*)&l0, *(uint32_t*)&l1 };
        ((uint2*)hi)[i] = ho;
        ((uint2*)lo)[i] = loo;
    }
}

__global__ __launch_bounds__(256) void transpose_split4(
    const float* __restrict__ W0, const float* __restrict__ W1,
    const float* __restrict__ W2, const float* __restrict__ W3,
    __nv_bfloat16* __restrict__ hi, __nv_bfloat16* __restrict__ lo)
{
    __shared__ float t[32][33];
    const int z = blockIdx.z;
    const float* W = (z == 0) ? W0 : (z == 1) ? W1 : (z == 2) ? W2 : W3;
    const size_t off = (size_t)z * H * H;
    const int tx = threadIdx.x, ty = threadIdx.y;   // (32, 8)
    const int bx = blockIdx.x, by = blockIdx.y;
    #pragma unroll
    for (int i = 0; i < 4; i++)
        t[ty + 8 * i][tx] = W[(size_t)(by * 32 + ty + 8 * i) * H + bx * 32 + tx];
    __syncthreads();
    #pragma unroll
    for (int i = 0; i < 4; i++) {
        float v = t[tx][ty + 8 * i];
        int n = bx * 32 + ty + 8 * i;
        int k = by * 32 + tx;
        __nv_bfloat16 h = __float2bfloat16(v);
        hi[off + (size_t)n * H + k] = h;
        lo[off + (size_t)n * H + k] = __float2bfloat16(v - __bfloat162float(h));
    }
}

// ---------------------------------------------------------------------------
// HMMA split-bf16 GEMM mainloop: 128x128 CTA tile, BK=32, 8 warps (2x4),
// 2-stage cp.async, one barrier per iter, x4 B loads, product-outer MMAs.
// ---------------------------------------------------------------------------
#define ROWB 80
#define TILEB (128 * ROWB)            // 10240
#define STAGEB (4 * TILEB)            // 40960
#define GEMM_SMEM (2 * STAGEB)        // 81920

__device__ __forceinline__ void gemm_mainloop(
    const __nv_bfloat16* __restrict__ Ahi, const __nv_bfloat16* __restrict__ Alo,
    const __nv_bfloat16* __restrict__ Bhi, const __nv_bfloat16* __restrict__ Blo,
    int m0, uint32_t sb, float acc[4][4][4])
{
    const int tid  = threadIdx.x;
    const int wid  = tid >> 5;
    const int lane = tid & 31;
    const int warp_m = wid >> 2;
    const int warp_n = wid & 3;

    const uint32_t a_row = (lane & 15);
    const uint32_t a_koff = (lane >> 4) * 16;
    const uint32_t b_row16 = (lane & 7) + ((lane >> 4) & 1) * 8;
    const uint32_t b_koff = ((lane >> 3) & 1) * 16;

    const int g_row0 = tid >> 2;
    const int g_u4   = tid & 3;

    auto load_stage = [&](int stage, int k0) {
        const uint32_t st = sb + stage * STAGEB;
        #pragma unroll
        for (int i = 0; i < 2; i++) {
            const int row = g_row0 + i * 64;
            const uint32_t so = (uint32_t)row * ROWB + g_u4 * 16;
            const size_t ga = (size_t)(m0 + row) * H + k0 + g_u4 * 8;
            const size_t gb = (size_t)row * H + k0 + g_u4 * 8;
            cp16(st + 0 * TILEB + so, Ahi + ga);
            cp16(st + 1 * TILEB + so, Alo + ga);
            cp16(st + 2 * TILEB + so, Bhi + gb);
            cp16(st + 3 * TILEB + so, Blo + gb);
        }
        cp_commit();
    };

    load_stage(0, 0);

    for (int kc = 0; kc < 32; kc++) {
        cp_wait<0>();
        __syncthreads();
        if (kc < 31) load_stage((kc + 1) & 1, (kc + 1) * 32);

        const uint32_t st = sb + (kc & 1) * STAGEB;
        const uint32_t S_AHI = st, S_ALO = st + TILEB,
                       S_BHI = st + 2 * TILEB, S_BLO = st + 3 * TILEB;

        #pragma unroll
        for (int ks = 0; ks < 2; ks++) {
            const uint32_t kb = ks * 32;
            uint32_t bh[4][2], bl[4][2];
            #pragma unroll
            for (int nfp = 0; nfp < 2; nfp++) {
                const uint32_t boff =
                    (uint32_t)(warp_n * 32 + nfp * 16 + b_row16) * ROWB + kb + b_koff;
                ldsm_x4(&bh[2 * nfp][0], S_BHI + boff);
                ldsm_x4(&bl[2 * nfp][0], S_BLO + boff);
            }
            #pragma unroll
            for (int mf = 0; mf < 4; mf++) {
                const uint32_t aoff =
                    (uint32_t)(warp_m * 64 + mf * 16 + a_row) * ROWB + kb + a_koff;
                uint32_t ah[4], al[4];
                ldsm_x4(ah, S_AHI + aoff);
                ldsm_x4(al, S_ALO + aoff);
                #pragma unroll
                for (int nf = 0; nf < 4; nf++) mma_bf16(acc[mf][nf], ah, bh[nf]);
                #pragma unroll
                for (int nf = 0; nf < 4; nf++) mma_bf16(acc[mf][nf], ah, bl[nf]);
                #pragma unroll
                for (int nf = 0; nf < 4; nf++) mma_bf16(acc[mf][nf], al, bh[nf]);
            }
        }
    }
}

// Fused QKV projection: B = concatenated [3072 x 1024] W^T.
__global__ __launch_bounds__(256, 2) void gemm_qkv(
    const __nv_bfloat16* __restrict__ Ahi, const __nv_bfloat16* __restrict__ Alo,
    const __nv_bfloat16* __restrict__ WThi, const __nv_bfloat16* __restrict__ WTlo,
    const float* __restrict__ bq, const float* __restrict__ bk,
    const float* __restrict__ bv,
    __nv_bfloat16* __restrict__ Qhi, __nv_bfloat16* __restrict__ Qlo,
    __nv_bfloat16* __restrict__ Khi, __nv_bfloat16* __restrict__ Klo,
    __nv_bfloat16* __restrict__ Vhi, __nv_bfloat16* __restrict__ Vlo)
{
    extern __shared__ __align__(16) char smem[];
    const uint32_t sb = smem_u32(smem);
    const int m0 = blockIdx.y * 128;
    const int n0 = blockIdx.x * 128;   // 0..2944

    float acc[4][4][4];
    #pragma unroll
    for (int i = 0; i < 4; i++)
        #pragma unroll
        for (int j = 0; j < 4; j++)
            #pragma unroll
            for (int r = 0; r < 4; r++) acc[i][j][r] = 0.0f;

    gemm_mainloop(Ahi, Alo, WThi + (size_t)n0 * H, WTlo + (size_t)n0 * H,
                  m0, sb, acc);

    const int sec = n0 >> 10;
    const float* bias = (sec == 0) ? bq : (sec == 1) ? bk : bv;
    const float scale = (sec == 0) ? QSCALE : 1.0f;
    __nv_bfloat16* Chi = (sec == 0) ? Qhi : (sec == 1) ? Khi : Vhi;
    __nv_bfloat16* Clo = (sec == 0) ? Qlo : (sec == 1) ? Klo : Vlo;
    const int nloc0 = n0 & 1023;

    const int tid  = threadIdx.x;
    const int wid  = tid >> 5;
    const int lane = tid & 31;
    const int warp_m = wid >> 2;
    const int warp_n = wid & 3;
    const int r_in = lane >> 2;
    const int c_in = (lane & 3) * 2;
    #pragma unroll
    for (int nf = 0; nf < 4; nf++) {
        const int col = nloc0 + warp_n * 32 + nf * 8 + c_in;
        const float2 bv2 = *(const float2*)(bias + col);
        #pragma unroll
        for (int mf = 0; mf < 4; mf++) {
            const int row = m0 + warp_m * 64 + mf * 16 + r_in;
            float v00 = (acc[mf][nf][0] + bv2.x) * scale;
            float v01 = (acc[mf][nf][1] + bv2.y) * scale;
            float v10 = (acc[mf][nf][2] + bv2.x) * scale;
            float v11 = (acc[mf][nf][3] + bv2.y) * scale;
            uint32_t h0, l0, h1, l1;
            split2(v00, v01, h0, l0);
            split2(v10, v11, h1, l1);
            *(uint32_t*)(Chi + (size_t)row * H + col) = h0;
            *(uint32_t*)(Clo + (size_t)row * H + col) = l0;
            *(uint32_t*)(Chi + (size_t)(row + 8) * H + col) = h1;
            *(uint32_t*)(Clo + (size_t)(row + 8) * H + col) = l1;
        }
    }
}

// Output projection: f32 out
__global__ __launch_bounds__(256, 2) void gemm_o(
    const __nv_bfloat16* __restrict__ Ahi, const __nv_bfloat16* __restrict__ Alo,
    const __nv_bfloat16* __restrict__ WThi, const __nv_bfloat16* __restrict__ WTlo,
    const float* __restrict__ bias, float* __restrict__ C)
{
    extern __shared__ __align__(16) char smem[];
    const uint32_t sb = smem_u32(smem);
    const int m0 = blockIdx.y * 128;
    const int n0 = blockIdx.x * 128;

    float acc[4][4][4];
    #pragma unroll
    for (int i = 0; i < 4; i++)
        #pragma unroll
        for (int j = 0; j < 4; j++)
            #pragma unroll
            for (int r = 0; r < 4; r++) acc[i][j][r] = 0.0f;

    gemm_mainloop(Ahi, Alo, WThi + (size_t)n0 * H, WTlo + (size_t)n0 * H,
                  m0, sb, acc);

    const int tid  = threadIdx.x;
    const int wid  = tid >> 5;
    const int lane = tid & 31;
    const int warp_m = wid >> 2;
    const int warp_n = wid & 3;
    const int r_in = lane >> 2;
    const int c_in = (lane & 3) * 2;
    #pragma unroll
    for (int nf = 0; nf < 4; nf++) {
        const int col = n0 + warp_n * 32 + nf * 8 + c_in;
        const float2 bv2 = *(const float2*)(bias + col);
        #pragma unroll
        for (int mf = 0; mf < 4; mf++) {
            const int row = m0 + warp_m * 64 + mf * 16 + r_in;
            float2 o0 = { acc[mf][nf][0] + bv2.x, acc[mf][nf][1] + bv2.y };
            float2 o1 = { acc[mf][nf][2] + bv2.x, acc[mf][nf][3] + bv2.y };
            *(float2*)(C + (size_t)row * H + col) = o0;
            *(float2*)(C + (size_t)(row + 8) * H + col) = o1;
        }
    }
}

// ---------------------------------------------------------------------------
// HMMA flash attention: Br=64 (4 warps, 128 thr), Bc=32 KV tiles, 2-stage
// cp.async, one barrier/iter. 55.3KB smem -> 3 CTAs/SM (12 warps), no spills.
// Heavy-first qb ordering. grid (SEQ/64, BSZ*NH).
// ---------------------------------------------------------------------------
#define AROW 144
#define QTILE (64 * AROW)              // 9216
#define KVTILE (32 * AROW)             // 4608
#define KVSTAGE (4 * KVTILE)           // 18432
#define ATTN_SMEM (2 * QTILE + 2 * KVSTAGE)   // 55296

__global__ __launch_bounds__(128, 3) void attn_hmma(
    const __nv_bfloat16* __restrict__ Qhi, const __nv_bfloat16* __restrict__ Qlo,
    const __nv_bfloat16* __restrict__ Khi, const __nv_bfloat16* __restrict__ Klo,
    const __nv_bfloat16* __restrict__ Vhi, const __nv_bfloat16* __restrict__ Vlo,
    __nv_bfloat16* __restrict__ Chi, __nv_bfloat16* __restrict__ Clo)
{
    extern __shared__ __align__(16) char smem[];
    const uint32_t sb = smem_u32(smem);
    const uint32_t S_QH = 0, S_QL = QTILE;

    const int tid  = threadIdx.x;
    const int warp = tid >> 5;
    const int lane = tid & 31;
    const int qb = gridDim.x - 1 - blockIdx.x;   // heavy tiles first
    const int b  = blockIdx.y / NH;
    const int h  = blockIdx.y % NH;
    const size_t hcol = (size_t)h * HD;
    const size_t rbase = (size_t)b * SEQ;

    // Q tile (64 x 64 bf16, hi+lo)
    #pragma unroll
    for (int t = 0; t < 4; t++) {
        const int idx = tid + t * 128;
        const int r = idx >> 3, c = idx & 7;
        const uint32_t so = (uint32_t)r * AROW + c * 16;
        const size_t g = (rbase + qb * 64 + r) * H + hcol + c * 8;
        cp16(sb + S_QH + so, Qhi + g);
        cp16(sb + S_QL + so, Qlo + g);
    }
    cp_commit();

    auto load_kv = [&](int stage, int kb) {
        const uint32_t st = sb + 2 * QTILE + stage * KVSTAGE;
        #pragma unroll
        for (int t = 0; t < 2; t++) {
            const int idx = tid + t * 128;      // 0..255
            const int r = idx >> 3, c = idx & 7;
            const uint32_t so = (uint32_t)r * AROW + c * 16;
            const size_t g = (rbase + kb * 32 + r) * H + hcol + c * 8;
            cp16(st + 0 * KVTILE + so, Khi + g);
            cp16(st + 1 * KVTILE + so, Klo + g);
            cp16(st + 2 * KVTILE + so, Vhi + g);
            cp16(st + 3 * KVTILE + so, Vlo + g);
        }
        cp_commit();
    };

    float O[8][4];
    #pragma unroll
    for (int d = 0; d < 8; d++)
        #pragma unroll
        for (int r = 0; r < 4; r++) O[d][r] = 0.0f;
    float m0 = -1e30f, m1 = -1e30f, l0 = 0.0f, l1 = 0.0f;

    const uint32_t a_base = S_QH + (uint32_t)(warp * 16 + (lane & 15)) * AROW
                          + (lane >> 4) * 16;
    const uint32_t al_base = a_base + QTILE;
    const uint32_t b_row16 = (lane & 7) + ((lane >> 4) & 1) * 8;
    const uint32_t b_koff = ((lane >> 3) & 1) * 16;

    const int r_in = lane >> 2;
    const int c_in = (lane & 3) * 2;

    const int nkb = 2 * qb + 2;
    load_kv(0, 0);

    for (int kb = 0; kb < nkb; kb++) {
        cp_wait<0>();
        __syncthreads();
        if (kb + 1 < nkb) load_kv((kb + 1) & 1, kb + 1);

        const uint32_t st = sb + 2 * QTILE + (kb & 1) * KVSTAGE;
        const uint32_t S_KH = st, S_KL = st + KVTILE,
                       S_VH = st + 2 * KVTILE, S_VL = st + 3 * KVTILE;

        float s[4][4];
        #pragma unroll
        for (int nf = 0; nf < 4; nf++)
            #pragma unroll
            for (int r = 0; r < 4; r++) s[nf][r] = 0.0f;

        // S = Q K^T; reusable K-frag buffer: K-hi -> (qh*kh, ql*kh),
        // overwrite with K-lo -> (qh*kl)
        #pragma unroll
        for (int ks = 0; ks < 4; ks++) {
            uint32_t ah[4], al[4], bb[4][2];
            ldsm_x4(ah, sb + a_base + ks * 32);
            ldsm_x4(al, sb + al_base + ks * 32);
            #pragma unroll
            for (int nfp = 0; nfp < 2; nfp++) {
                const uint32_t bo =
                    (uint32_t)(nfp * 16 + b_row16) * AROW + ks * 32 + b_koff;
                ldsm_x4(&bb[2 * nfp][0], S_KH + bo);
            }
            #pragma unroll
            for (int nf = 0; nf < 4; nf++) mma_bf16(s[nf], ah, bb[nf]);
            #pragma unroll
            for (int nf = 0; nf < 4; nf++) mma_bf16(s[nf], al, bb[nf]);
            #pragma unroll
            for (int nfp = 0; nfp < 2; nfp++) {
                const uint32_t bo =
                    (uint32_t)(nfp * 16 + b_row16) * AROW + ks * 32 + b_koff;
                ldsm_x4(&bb[2 * nfp][0], S_KL + bo);
            }
            #pragma unroll
            for (int nf = 0; nf < 4; nf++) mma_bf16(s[nf], ah, bb[nf]);
        }

        if (kb >= 2 * qb) {   // tiles overlapping the diagonal
            const int row0 = qb * 64 + warp * 16 + r_in;
            const int row1 = row0 + 8;
            #pragma unroll
            for (int nf = 0; nf < 4; nf++) {
                const int cg = kb * 32 + nf * 8 + c_in;
                if (cg > row0)     s[nf][0] = -1e30f;
                if (cg + 1 > row0) s[nf][1] = -1e30f;
                if (cg > row1)     s[nf][2] = -1e30f;
                if (cg + 1 > row1) s[nf][3] = -1e30f;
            }
        }

        float rmax0 = -1e30f, rmax1 = -1e30f;
        #pragma unroll
        for (int nf = 0; nf < 4; nf++) {
            rmax0 = fmaxf(rmax0, fmaxf(s[nf][0], s[nf][1]));
            rmax1 = fmaxf(rmax1, fmaxf(s[nf][2], s[nf][3]));
        }
        rmax0 = fmaxf(rmax0, __shfl_xor_sync(0xffffffffu, rmax0, 1));
        rmax0 = fmaxf(rmax0, __shfl_xor_sync(0xffffffffu, rmax0, 2));
        rmax1 = fmaxf(rmax1, __shfl_xor_sync(0xffffffffu, rmax1, 1));
        rmax1 = fmaxf(rmax1, __shfl_xor_sync(0xffffffffu, rmax1, 2));
        const float mn0 = fmaxf(m0, rmax0);
        const float mn1 = fmaxf(m1, rmax1);
        const float sc0 = exp2a(m0 - mn0);
        const float sc1 = exp2a(m1 - mn1);

        float rs0 = 0.0f, rs1 = 0.0f;
        #pragma unroll
        for (int nf = 0; nf < 4; nf++) {
            s[nf][0] = exp2a(s[nf][0] - mn0);
            s[nf][1] = exp2a(s[nf][1] - mn0);
            s[nf][2] = exp2a(s[nf][2] - mn1);
            s[nf][3] = exp2a(s[nf][3] - mn1);
            rs0 += s[nf][0] + s[nf][1];
            rs1 += s[nf][2] + s[nf][3];
        }
        rs0 += __shfl_xor_sync(0xffffffffu, rs0, 1);
        rs0 += __shfl_xor_sync(0xffffffffu, rs0, 2);
        rs1 += __shfl_xor_sync(0xffffffffu, rs1, 1);
        rs1 += __shfl_xor_sync(0xffffffffu, rs1, 2);
        l0 = l0 * sc0 + rs0;
        l1 = l1 * sc1 + rs1;
        m0 = mn0; m1 = mn1;
        #pragma unroll
        for (int d = 0; d < 8; d++) {
            O[d][0] *= sc0; O[d][1] *= sc0;
            O[d][2] *= sc1; O[d][3] *= sc1;
        }

        // O += P V (P split on the fly; x4.trans V loads over the 32 kv rows)
        {
            uint32_t ph0[4], pl0[4], ph1[4], pl1[4];
            split2(s[0][0], s[0][1], ph0[0], pl0[0]);
            split2(s[0][2], s[0][3], ph0[1], pl0[1]);
            split2(s[1][0], s[1][1], ph0[2], pl0[2]);
            split2(s[1][2], s[1][3], ph0[3], pl0[3]);
            split2(s[2][0], s[2][1], ph1[0], pl1[0]);
            split2(s[2][2], s[2][3], ph1[1], pl1[1]);
            split2(s[3][0], s[3][1], ph1[2], pl1[2]);
            split2(s[3][2], s[3][3], ph1[3], pl1[3]);

            const uint32_t vrow = (uint32_t)lane * AROW;
            #pragma unroll
            for (int dfp = 0; dfp < 4; dfp++) {
                const int df0 = 2 * dfp, df1 = 2 * dfp + 1;
                uint32_t vha[4], vla[4], vhb[4], vlb[4];
                ldsm_x4t(vha, S_VH + vrow + df0 * 16);
                ldsm_x4t(vla, S_VL + vrow + df0 * 16);
                ldsm_x4t(vhb, S_VH + vrow + df1 * 16);
                ldsm_x4t(vlb, S_VL + vrow + df1 * 16);
                mma_bf16(O[df0], ph0, &vha[0]);
                mma_bf16(O[df1], ph0, &vhb[0]);
                mma_bf16(O[df0], ph1, &vha[2]);
                mma_bf16(O[df1], ph1, &vhb[2]);
                mma_bf16(O[df0], ph0, &vla[0]);
                mma_bf16(O[df1], ph0, &vlb[0]);
                mma_bf16(O[df0], ph1, &vla[2]);
                mma_bf16(O[df1], ph1, &vlb[2]);
                mma_bf16(O[df0], pl0, &vha[0]);
                mma_bf16(O[df1], pl0, &vhb[0]);
                mma_bf16(O[df0], pl1, &vha[2]);
                mma_bf16(O[df1], pl1, &vhb[2]);
            }
        }
    }

    const float inv0 = 1.0f / l0;
    const float inv1 = 1.0f / l1;
    const int row0 = qb * 64 + warp * 16 + r_in;
    #pragma unroll
    for (int df = 0; df < 8; df++) {
        const size_t col = hcol + df * 8 + c_in;
        uint32_t h0, lo0, h1, lo1;
        split2(O[df][0] * inv0, O[df][1] * inv0, h0, lo0);
        split2(O[df][2] * inv1, O[df][3] * inv1, h1, lo1);
        *(uint32_t*)(Chi + (rbase + row0) * H + col) = h0;
        *(uint32_t*)(Clo + (rbase + row0) * H + col) = lo0;
        *(uint32_t*)(Chi + (rbase + row0 + 8) * H + col) = h1;
        *(uint32_t*)(Clo + (rbase + row0 + 8) * H + col) = lo1;
    }
}

// ---------------------------------------------------------------------------
extern "C" void kernel_launch(void* const* d_in, const int* in_sizes, int n_in,
                              void* d_out, int out_size)
{
    const float* x  = (const float*)d_in[0];
    const float* Wq = (const float*)d_in[1];
    const float* bq = (const float*)d_in[2];
    const float* Wk = (const float*)d_in[3];
    const float* bk = (const float*)d_in[4];
    const float* Wv = (const float*)d_in[5];
    const float* bv = (const float*)d_in[6];
    const float* Wo = (const float*)d_in[7];
    const float* bo = (const float*)d_in[8];
    float* out = (float*)d_out;

    cudaFuncSetAttribute(gemm_qkv,
                         cudaFuncAttributeMaxDynamicSharedMemorySize, GEMM_SMEM);
    cudaFuncSetAttribute(gemm_o,
                         cudaFuncAttributeMaxDynamicSharedMemorySize, GEMM_SMEM);
    cudaFuncSetAttribute(attn_hmma,
                         cudaFuncAttributeMaxDynamicSharedMemorySize, ATTN_SMEM);

    __nv_bfloat16 *qhi, *qlo, *khi, *klo, *vhi, *vlo, *chi, *clo;
    __nv_bfloat16 *xhi, *xlo, *wthi, *wtlo;
    cudaGetSymbolAddress((void**)&qhi, g_Qhi);
    cudaGetSymbolAddress((void**)&qlo, g_Qlo);
    cudaGetSymbolAddress((void**)&khi, g_Khi);
    cudaGetSymbolAddress((void**)&klo, g_Klo);
    cudaGetSymbolAddress((void**)&vhi, g_Vhi);
    cudaGetSymbolAddress((void**)&vlo, g_Vlo);
    cudaGetSymbolAddress((void**)&chi, g_chi);
    cudaGetSymbolAddress((void**)&clo, g_clo);
    cudaGetSymbolAddress((void**)&xhi, g_xhi);
    cudaGetSymbolAddress((void**)&xlo, g_xlo);
    cudaGetSymbolAddress((void**)&wthi, g_WThi);
    cudaGetSymbolAddress((void**)&wtlo, g_WTlo);

    const int nelem = MTOT * H;
    const size_t WSZ = (size_t)H * H;

    split_bf16_v4<<<(nelem / 4 + 255) / 256, 256>>>(x, xhi, xlo, nelem / 4);
    dim3 tgrid(H / 32, H / 32, 4), tblk(32, 8);
    transpose_split4<<<tgrid, tblk>>>(Wq, Wk, Wv, Wo, wthi, wtlo);

    dim3 qkvgrid(3 * H / 128, MTOT / 128);   // (24, 32)
    gemm_qkv<<<qkvgrid, 256, GEMM_SMEM>>>(xhi, xlo, wthi, wtlo,
        bq, bk, bv, qhi, qlo, khi, klo, vhi, vlo);

    dim3 agrid(SEQ / 64, BSZ * NH);          // (32, 32)
    attn_hmma<<<agrid, 128, ATTN_SMEM>>>(qhi, qlo, khi, klo, vhi, vlo, chi, clo);

    dim3 ogrid(H / 128, MTOT / 128);         // (8, 32)
    gemm_o<<<ogrid, 256, GEMM_SMEM>>>(chi, clo, wthi + 3 * WSZ, wtlo + 3 * WSZ,
                                      bo, out);
}

// round 11
// speedup vs baseline: 1.3597x; 1.2890x over previous
#include <cuda_runtime.h>
#include <cuda_fp16.h>
#include <math.h>
#include <stdint.h>

#define H   1024
#define NH  16
#define HD  64
#define BSZ 2
#define SEQ 2048
#define MTOT (BSZ*SEQ)   // 4096 rows

// 0.125 (1/sqrt(HD)) * log2(e): folded into Q projection
#define QSCALE 0.18033688011112042f

// ---------------------------------------------------------------------------
// Scratch (allocation-free rule: __device__ globals) — all fp16 now
// ---------------------------------------------------------------------------
__device__ __half g_Qh [MTOT * H];           // Q hi only (1-term path)
__device__ __half g_Kh [MTOT * H];           // K hi only
__device__ __half g_Vhi[MTOT * H];
__device__ __half g_Vlo[MTOT * H];
__device__ __half g_chi[MTOT * H];
__device__ __half g_clo[MTOT * H];
__device__ __half g_xhi[MTOT * H];
__device__ __half g_xlo[MTOT * H];
__device__ __half g_WThi[4][H * H];          // W^T (q,k,v,o), fp16-hi
__device__ __half g_WTlo[4][H * H];          // W^T, fp16-lo

// ---------------------------------------------------------------------------
// helpers
// ---------------------------------------------------------------------------
__device__ __forceinline__ uint32_t smem_u32(const void* p) {
    uint32_t a;
    asm("{ .reg .u64 t; cvta.to.shared.u64 t, %1; cvt.u32.u64 %0, t; }"
        : "=r"(a) : "l"(p));
    return a;
}
__device__ __forceinline__ void ldsm_x4(uint32_t* r, uint32_t addr) {
    asm volatile("ldmatrix.sync.aligned.m8n8.x4.shared.b16 {%0,%1,%2,%3}, [%4];"
                 : "=r"(r[0]), "=r"(r[1]), "=r"(r[2]), "=r"(r[3]) : "r"(addr));
}
__device__ __forceinline__ void ldsm_x4t(uint32_t* r, uint32_t addr) {
    asm volatile("ldmatrix.sync.aligned.m8n8.x4.trans.shared.b16 {%0,%1,%2,%3}, [%4];"
                 : "=r"(r[0]), "=r"(r[1]), "=r"(r[2]), "=r"(r[3]) : "r"(addr));
}
__device__ __forceinline__ void mma_f16(float* c, const uint32_t* a,
                                        const uint32_t* b) {
    asm volatile(
        "mma.sync.aligned.m16n8k16.row.col.f32.f16.f16.f32 "
        "{%0,%1,%2,%3}, {%4,%5,%6,%7}, {%8,%9}, {%0,%1,%2,%3};"
        : "+f"(c[0]), "+f"(c[1]), "+f"(c[2]), "+f"(c[3])
        : "r"(a[0]), "r"(a[1]), "r"(a[2]), "r"(a[3]), "r"(b[0]), "r"(b[1]));
}
__device__ __forceinline__ float exp2a(float x) {
    float y;
    asm("ex2.approx.f32 %0, %1;" : "=f"(y) : "f"(x));
    return y;
}
// pack two floats -> fp16x2 hi + fp16x2 residual lo
__device__ __forceinline__ void split2h(float a, float b, uint32_t& hi, uint32_t& lo) {
    __half2 h = __floats2half2_rn(a, b);
    float ra = a - __half2float(__low2half(h));
    float rb = b - __half2float(__high2half(h));
    __half2 l = __floats2half2_rn(ra, rb);
    hi = *(uint32_t*)&h;
    lo = *(uint32_t*)&l;
}
__device__ __forceinline__ uint32_t pack2h(float a, float b) {
    __half2 h = __floats2half2_rn(a, b);
    return *(uint32_t*)&h;
}
__device__ __forceinline__ void cp16(uint32_t saddr, const void* g) {
    asm volatile("cp.async.cg.shared.global [%0], [%1], 16;"
                 :: "r"(saddr), "l"(g) : "memory");
}
__device__ __forceinline__ void cp_commit() {
    asm volatile("cp.async.commit_group;" ::: "memory");
}
template <int N>
__device__ __forceinline__ void cp_wait() {
    asm volatile("cp.async.wait_group %0;" :: "n"(N) : "memory");
}

// ---------------------------------------------------------------------------
// Prep
// ---------------------------------------------------------------------------
__global__ __launch_bounds__(256) void split_f16_v4(
    const float* __restrict__ src, __half* __restrict__ hi,
    __half* __restrict__ lo, int n4)
{
    int i = blockIdx.x * 256 + threadIdx.x;
    if (i < n4) {
        float4 v = ((const float4*)src)[i];
        uint32_t h0, l0, h1, l1;
        split2h(v.x, v.y, h0, l0);
        split2h(v.z, v.w, h1, l1);
        uint2 ho = { h0, h1 };
        uint2 loo = { l0, l1 };
        ((uint2*)hi)[i] = ho;
        ((uint2*)lo)[i] = loo;
    }
}

__global__ __launch_bounds__(256) void transpose_split4(
    const float* __restrict__ W0, const float* __restrict__ W1,
    const float* __restrict__ W2, const float* __restrict__ W3,
    __half* __restrict__ hi, __half* __restrict__ lo)
{
    __shared__ float t[32][33];
    const int z = blockIdx.z;
    const float* W = (z == 0) ? W0 : (z == 1) ? W1 : (z == 2) ? W2 : W3;
    const size_t off = (size_t)z * H * H;
    const int tx = threadIdx.x, ty = threadIdx.y;   // (32, 8)
    const int bx = blockIdx.x, by = blockIdx.y;
    #pragma unroll
    for (int i = 0; i < 4; i++)
        t[ty + 8 * i][tx] = W[(size_t)(by * 32 + ty + 8 * i) * H + bx * 32 + tx];
    __syncthreads();
    #pragma unroll
    for (int i = 0; i < 4; i++) {
        float v = t[tx][ty + 8 * i];
        int n = bx * 32 + ty + 8 * i;
        int k = by * 32 + tx;
        __half h = __float2half_rn(v);
        hi[off + (size_t)n * H + k] = h;
        lo[off + (size_t)n * H + k] = __float2half_rn(v - __half2float(h));
    }
}

// ---------------------------------------------------------------------------
// HMMA fp16 GEMM mainloop: 128x128 CTA tile, BK=32, 8 warps (2x4),
// 2-stage cp.async, one barrier per iter. nterms: 1 = hi*hi only,
// 3 = hi*hi + hi*lo + lo*hi (split-fp16 compensated).
// ---------------------------------------------------------------------------
#define ROWB 80
#define TILEB (128 * ROWB)            // 10240
#define STAGEB (4 * TILEB)            // 40960
#define GEMM_SMEM (2 * STAGEB)        // 81920

__device__ __forceinline__ void gemm_mainloop(
    const __half* __restrict__ Ahi, const __half* __restrict__ Alo,
    const __half* __restrict__ Bhi, const __half* __restrict__ Blo,
    int m0, uint32_t sb, float acc[4][4][4], int nterms)
{
    const int tid  = threadIdx.x;
    const int wid  = tid >> 5;
    const int lane = tid & 31;
    const int warp_m = wid >> 2;
    const int warp_n = wid & 3;

    const uint32_t a_row = (lane & 15);
    const uint32_t a_koff = (lane >> 4) * 16;
    const uint32_t b_row16 = (lane & 7) + ((lane >> 4) & 1) * 8;
    const uint32_t b_koff = ((lane >> 3) & 1) * 16;

    const int g_row0 = tid >> 2;
    const int g_u4   = tid & 3;

    auto load_stage = [&](int stage, int k0) {
        const uint32_t st = sb + stage * STAGEB;
        #pragma unroll
        for (int i = 0; i < 2; i++) {
            const int row = g_row0 + i * 64;
            const uint32_t so = (uint32_t)row * ROWB + g_u4 * 16;
            const size_t ga = (size_t)(m0 + row) * H + k0 + g_u4 * 8;
            const size_t gb = (size_t)row * H + k0 + g_u4 * 8;
            cp16(st + 0 * TILEB + so, Ahi + ga);
            cp16(st + 2 * TILEB + so, Bhi + gb);
            if (nterms == 3) {
                cp16(st + 1 * TILEB + so, Alo + ga);
                cp16(st + 3 * TILEB + so, Blo + gb);
            }
        }
        cp_commit();
    };

    load_stage(0, 0);

    for (int kc = 0; kc < 32; kc++) {
        cp_wait<0>();
        __syncthreads();
        if (kc < 31) load_stage((kc + 1) & 1, (kc + 1) * 32);

        const uint32_t st = sb + (kc & 1) * STAGEB;
        const uint32_t S_AHI = st, S_ALO = st + TILEB,
                       S_BHI = st + 2 * TILEB, S_BLO = st + 3 * TILEB;

        #pragma unroll
        for (int ks = 0; ks < 2; ks++) {
            const uint32_t kb = ks * 32;
            uint32_t bh[4][2];
            #pragma unroll
            for (int nfp = 0; nfp < 2; nfp++) {
                const uint32_t boff =
                    (uint32_t)(warp_n * 32 + nfp * 16 + b_row16) * ROWB + kb + b_koff;
                ldsm_x4(&bh[2 * nfp][0], S_BHI + boff);
            }
            if (nterms == 1) {
                #pragma unroll
                for (int mf = 0; mf < 4; mf++) {
                    const uint32_t aoff =
                        (uint32_t)(warp_m * 64 + mf * 16 + a_row) * ROWB + kb + a_koff;
                    uint32_t ah[4];
                    ldsm_x4(ah, S_AHI + aoff);
                    #pragma unroll
                    for (int nf = 0; nf < 4; nf++) mma_f16(acc[mf][nf], ah, bh[nf]);
                }
            } else {
                uint32_t bl[4][2];
                #pragma unroll
                for (int nfp = 0; nfp < 2; nfp++) {
                    const uint32_t boff =
                        (uint32_t)(warp_n * 32 + nfp * 16 + b_row16) * ROWB + kb + b_koff;
                    ldsm_x4(&bl[2 * nfp][0], S_BLO + boff);
                }
                #pragma unroll
                for (int mf = 0; mf < 4; mf++) {
                    const uint32_t aoff =
                        (uint32_t)(warp_m * 64 + mf * 16 + a_row) * ROWB + kb + a_koff;
                    uint32_t ah[4], al[4];
                    ldsm_x4(ah, S_AHI + aoff);
                    ldsm_x4(al, S_ALO + aoff);
                    #pragma unroll
                    for (int nf = 0; nf < 4; nf++) mma_f16(acc[mf][nf], ah, bh[nf]);
                    #pragma unroll
                    for (int nf = 0; nf < 4; nf++) mma_f16(acc[mf][nf], ah, bl[nf]);
                    #pragma unroll
                    for (int nf = 0; nf < 4; nf++) mma_f16(acc[mf][nf], al, bh[nf]);
                }
            }
        }
    }
}

// Fused QKV projection. Q,K sections: 1-term, store hi only.
// V section: 3-term, store hi+lo.
__global__ __launch_bounds__(256, 2) void gemm_qkv(
    const __half* __restrict__ Ahi, const __half* __restrict__ Alo,
    const __half* __restrict__ WThi, const __half* __restrict__ WTlo,
    const float* __restrict__ bq, const float* __restrict__ bk,
    const float* __restrict__ bv,
    __half* __restrict__ Qh, __half* __restrict__ Kh,
    __half* __restrict__ Vhi, __half* __restrict__ Vlo)
{
    extern __shared__ __align__(16) char smem[];
    const uint32_t sb = smem_u32(smem);
    const int m0 = blockIdx.y * 128;
    const int n0 = blockIdx.x * 128;   // 0..2944
    const int sec = n0 >> 10;
    const int nterms = (sec == 2) ? 3 : 1;

    float acc[4][4][4];
    #pragma unroll
    for (int i = 0; i < 4; i++)
        #pragma unroll
        for (int j = 0; j < 4; j++)
            #pragma unroll
            for (int r = 0; r < 4; r++) acc[i][j][r] = 0.0f;

    gemm_mainloop(Ahi, Alo, WThi + (size_t)n0 * H, WTlo + (size_t)n0 * H,
                  m0, sb, acc, nterms);

    const float* bias = (sec == 0) ? bq : (sec == 1) ? bk : bv;
    const float scale = (sec == 0) ? QSCALE : 1.0f;
    const int nloc0 = n0 & 1023;

    const int tid  = threadIdx.x;
    const int wid  = tid >> 5;
    const int lane = tid & 31;
    const int warp_m = wid >> 2;
    const int warp_n = wid & 3;
    const int r_in = lane >> 2;
    const int c_in = (lane & 3) * 2;
    #pragma unroll
    for (int nf = 0; nf < 4; nf++) {
        const int col = nloc0 + warp_n * 32 + nf * 8 + c_in;
        const float2 bv2 = *(const float2*)(bias + col);
        #pragma unroll
        for (int mf = 0; mf < 4; mf++) {
            const int row = m0 + warp_m * 64 + mf * 16 + r_in;
            float v00 = (acc[mf][nf][0] + bv2.x) * scale;
            float v01 = (acc[mf][nf][1] + bv2.y) * scale;
            float v10 = (acc[mf][nf][2] + bv2.x) * scale;
            float v11 = (acc[mf][nf][3] + bv2.y) * scale;
            if (sec == 2) {
                uint32_t h0, l0, h1, l1;
                split2h(v00, v01, h0, l0);
                split2h(v10, v11, h1, l1);
                *(uint32_t*)(Vhi + (size_t)row * H + col) = h0;
                *(uint32_t*)(Vlo + (size_t)row * H + col) = l0;
                *(uint32_t*)(Vhi + (size_t)(row + 8) * H + col) = h1;
                *(uint32_t*)(Vlo + (size_t)(row + 8) * H + col) = l1;
            } else {
                __half* C = (sec == 0) ? Qh : Kh;
                *(uint32_t*)(C + (size_t)row * H + col) = pack2h(v00, v01);
                *(uint32_t*)(C + (size_t)(row + 8) * H + col) = pack2h(v10, v11);
            }
        }
    }
}

// Output projection: 3-term, f32 out
__global__ __launch_bounds__(256, 2) void gemm_o(
    const __half* __restrict__ Ahi, const __half* __restrict__ Alo,
    const __half* __restrict__ WThi, const __half* __restrict__ WTlo,
    const float* __restrict__ bias, float* __restrict__ C)
{
    extern __shared__ __align__(16) char smem[];
    const uint32_t sb = smem_u32(smem);
    const int m0 = blockIdx.y * 128;
    const int n0 = blockIdx.x * 128;

    float acc[4][4][4];
    #pragma unroll
    for (int i = 0; i < 4; i++)
        #pragma unroll
        for (int j = 0; j < 4; j++)
            #pragma unroll
            for (int r = 0; r < 4; r++) acc[i][j][r] = 0.0f;

    gemm_mainloop(Ahi, Alo, WThi + (size_t)n0 * H, WTlo + (size_t)n0 * H,
                  m0, sb, acc, 3);

    const int tid  = threadIdx.x;
    const int wid  = tid >> 5;
    const int lane = tid & 31;
    const int warp_m = wid >> 2;
    const int warp_n = wid & 3;
    const int r_in = lane >> 2;
    const int c_in = (lane & 3) * 2;
    #pragma unroll
    for (int nf = 0; nf < 4; nf++) {
        const int col = n0 + warp_n * 32 + nf * 8 + c_in;
        const float2 bv2 = *(const float2*)(bias + col);
        #pragma unroll
        for (int mf = 0; mf < 4; mf++) {
            const int row = m0 + warp_m * 64 + mf * 16 + r_in;
            float2 o0 = { acc[mf][nf][0] + bv2.x, acc[mf][nf][1] + bv2.y };
            float2 o1 = { acc[mf][nf][2] + bv2.x, acc[mf][nf][3] + bv2.y };
            *(float2*)(C + (size_t)row * H + col) = o0;
            *(float2*)(C + (size_t)(row + 8) * H + col) = o1;
        }
    }
}

// ---------------------------------------------------------------------------
// fp16 HMMA flash attention: Br=64 (4 warps), Bc=32, 2-stage cp.async.
// QK: single product (Qh*Kh). PV: 3-term (Ph*Vh + Ph*Vl + Pl*Vh).
// Smem 36.9KB -> 3 CTAs/SM. Heavy-first qb ordering.
// ---------------------------------------------------------------------------
#define AROW 144
#define QTILE (64 * AROW)              // 9216
#define KVTILE (32 * AROW)             // 4608
#define KVSTAGE (3 * KVTILE)           // 13824 (Kh, Vh, Vl)
#define ATTN_SMEM (QTILE + 2 * KVSTAGE)   // 36864

__global__ __launch_bounds__(128, 3) void attn_hmma(
    const __half* __restrict__ Qh, const __half* __restrict__ Kh,
    const __half* __restrict__ Vhi, const __half* __restrict__ Vlo,
    __half* __restrict__ Chi, __half* __restrict__ Clo)
{
    extern __shared__ __align__(16) char smem[];
    const uint32_t sb = smem_u32(smem);
    const uint32_t S_QH = 0;

    const int tid  = threadIdx.x;
    const int warp = tid >> 5;
    const int lane = tid & 31;
    const int qb = gridDim.x - 1 - blockIdx.x;   // heavy tiles first
    const int b  = blockIdx.y / NH;
    const int h  = blockIdx.y % NH;
    const size_t hcol = (size_t)h * HD;
    const size_t rbase = (size_t)b * SEQ;

    // Q tile (64 x 64 fp16, hi only)
    #pragma unroll
    for (int t = 0; t < 4; t++) {
        const int idx = tid + t * 128;
        const int r = idx >> 3, c = idx & 7;
        const uint32_t so = (uint32_t)r * AROW + c * 16;
        const size_t g = (rbase + qb * 64 + r) * H + hcol + c * 8;
        cp16(sb + S_QH + so, Qh + g);
    }
    cp_commit();

    auto load_kv = [&](int stage, int kb) {
        const uint32_t st = sb + QTILE + stage * KVSTAGE;
        #pragma unroll
        for (int t = 0; t < 2; t++) {
            const int idx = tid + t * 128;      // 0..255
            const int r = idx >> 3, c = idx & 7;
            const uint32_t so = (uint32_t)r * AROW + c * 16;
            const size_t g = (rbase + kb * 32 + r) * H + hcol + c * 8;
            cp16(st + 0 * KVTILE + so, Kh + g);
            cp16(st + 1 * KVTILE + so, Vhi + g);
            cp16(st + 2 * KVTILE + so, Vlo + g);
        }
        cp_commit();
    };

    float O[8][4];
    #pragma unroll
    for (int d = 0; d < 8; d++)
        #pragma unroll
        for (int r = 0; r < 4; r++) O[d][r] = 0.0f;
    float m0 = -1e30f, m1 = -1e30f, l0 = 0.0f, l1 = 0.0f;

    const uint32_t a_base = S_QH + (uint32_t)(warp * 16 + (lane & 15)) * AROW
                          + (lane >> 4) * 16;
    const uint32_t b_row16 = (lane & 7) + ((lane >> 4) & 1) * 8;
    const uint32_t b_koff = ((lane >> 3) & 1) * 16;

    const int r_in = lane >> 2;
    const int c_in = (lane & 3) * 2;

    const int nkb = 2 * qb + 2;
    load_kv(0, 0);

    for (int kb = 0; kb < nkb; kb++) {
        cp_wait<0>();
        __syncthreads();
        if (kb + 1 < nkb) load_kv((kb + 1) & 1, kb + 1);

        const uint32_t st = sb + QTILE + (kb & 1) * KVSTAGE;
        const uint32_t S_KH = st, S_VH = st + KVTILE, S_VL = st + 2 * KVTILE;

        float s[4][4];
        #pragma unroll
        for (int nf = 0; nf < 4; nf++)
            #pragma unroll
            for (int r = 0; r < 4; r++) s[nf][r] = 0.0f;

        // S = Q K^T, single fp16 product
        #pragma unroll
        for (int ks = 0; ks < 4; ks++) {
            uint32_t ah[4], bb[4][2];
            ldsm_x4(ah, sb + a_base + ks * 32);
            #pragma unroll
            for (int nfp = 0; nfp < 2; nfp++) {
                const uint32_t bo =
                    (uint32_t)(nfp * 16 + b_row16) * AROW + ks * 32 + b_koff;
                ldsm_x4(&bb[2 * nfp][0], S_KH + bo);
            }
            #pragma unroll
            for (int nf = 0; nf < 4; nf++) mma_f16(s[nf], ah, bb[nf]);
        }

        if (kb >= 2 * qb) {   // tiles overlapping the diagonal
            const int row0 = qb * 64 + warp * 16 + r_in;
            const int row1 = row0 + 8;
            #pragma unroll
            for (int nf = 0; nf < 4; nf++) {
                const int cg = kb * 32 + nf * 8 + c_in;
                if (cg > row0)     s[nf][0] = -1e30f;
                if (cg + 1 > row0) s[nf][1] = -1e30f;
                if (cg > row1)     s[nf][2] = -1e30f;
                if (cg + 1 > row1) s[nf][3] = -1e30f;
            }
        }

        float rmax0 = -1e30f, rmax1 = -1e30f;
        #pragma unroll
        for (int nf = 0; nf < 4; nf++) {
            rmax0 = fmaxf(rmax0, fmaxf(s[nf][0], s[nf][1]));
            rmax1 = fmaxf(rmax1, fmaxf(s[nf][2], s[nf][3]));
        }
        rmax0 = fmaxf(rmax0, __shfl_xor_sync(0xffffffffu, rmax0, 1));
        rmax0 = fmaxf(rmax0, __shfl_xor_sync(0xffffffffu, rmax0, 2));
        rmax1 = fmaxf(rmax1, __shfl_xor_sync(0xffffffffu, rmax1, 1));
        rmax1 = fmaxf(rmax1, __shfl_xor_sync(0xffffffffu, rmax1, 2));
        const float mn0 = fmaxf(m0, rmax0);
        const float mn1 = fmaxf(m1, rmax1);
        const float sc0 = exp2a(m0 - mn0);
        const float sc1 = exp2a(m1 - mn1);

        float rs0 = 0.0f, rs1 = 0.0f;
        #pragma unroll
        for (int nf = 0; nf < 4; nf++) {
            s[nf][0] = exp2a(s[nf][0] - mn0);
            s[nf][1] = exp2a(s[nf][1] - mn0);
            s[nf][2] = exp2a(s[nf][2] - mn1);
            s[nf][3] = exp2a(s[nf][3] - mn1);
            rs0 += s[nf][0] + s[nf][1];
            rs1 += s[nf][2] + s[nf][3];
        }
        rs0 += __shfl_xor_sync(0xffffffffu, rs0, 1);
        rs0 += __shfl_xor_sync(0xffffffffu, rs0, 2);
        rs1 += __shfl_xor_sync(0xffffffffu, rs1, 1);
        rs1 += __shfl_xor_sync(0xffffffffu, rs1, 2);
        l0 = l0 * sc0 + rs0;
        l1 = l1 * sc1 + rs1;
        m0 = mn0; m1 = mn1;
        #pragma unroll
        for (int d = 0; d < 8; d++) {
            O[d][0] *= sc0; O[d][1] *= sc0;
            O[d][2] *= sc1; O[d][3] *= sc1;
        }

        // O += P V : 3-term (Ph*Vh + Ph*Vl + Pl*Vh), P split on the fly
        {
            uint32_t ph0[4], pl0[4], ph1[4], pl1[4];
            split2h(s[0][0], s[0][1], ph0[0], pl0[0]);
            split2h(s[0][2], s[0][3], ph0[1], pl0[1]);
            split2h(s[1][0], s[1][1], ph0[2], pl0[2]);
            split2h(s[1][2], s[1][3], ph0[3], pl0[3]);
            split2h(s[2][0], s[2][1], ph1[0], pl1[0]);
            split2h(s[2][2], s[2][3], ph1[1], pl1[1]);
            split2h(s[3][0], s[3][1], ph1[2], pl1[2]);
            split2h(s[3][2], s[3][3], ph1[3], pl1[3]);

            const uint32_t vrow = (uint32_t)lane * AROW;
            #pragma unroll
            for (int dfp = 0; dfp < 4; dfp++) {
                const int df0 = 2 * dfp, df1 = 2 * dfp + 1;
                uint32_t vha[4], vla[4], vhb[4], vlb[4];
                ldsm_x4t(vha, S_VH + vrow + df0 * 16);
                ldsm_x4t(vla, S_VL + vrow + df0 * 16);
                ldsm_x4t(vhb, S_VH + vrow + df1 * 16);
                ldsm_x4t(vlb, S_VL + vrow + df1 * 16);
                mma_f16(O[df0], ph0, &vha[0]);
                mma_f16(O[df1], ph0, &vhb[0]);
                mma_f16(O[df0], ph1, &vha[2]);
                mma_f16(O[df1], ph1, &vhb[2]);
                mma_f16(O[df0], ph0, &vla[0]);
                mma_f16(O[df1], ph0, &vlb[0]);
                mma_f16(O[df0], ph1, &vla[2]);
                mma_f16(O[df1], ph1, &vlb[2]);
                mma_f16(O[df0], pl0, &vha[0]);
                mma_f16(O[df1], pl0, &vhb[0]);
                mma_f16(O[df0], pl1, &vha[2]);
                mma_f16(O[df1], pl1, &vhb[2]);
            }
        }
    }

    const float inv0 = 1.0f / l0;
    const float inv1 = 1.0f / l1;
    const int row0 = qb * 64 + warp * 16 + r_in;
    #pragma unroll
    for (int df = 0; df < 8; df++) {
        const size_t col = hcol + df * 8 + c_in;
        uint32_t h0, lo0, h1, lo1;
        split2h(O[df][0] * inv0, O[df][1] * inv0, h0, lo0);
        split2h(O[df][2] * inv1, O[df][3] * inv1, h1, lo1);
        *(uint32_t*)(Chi + (rbase + row0) * H + col) = h0;
        *(uint32_t*)(Clo + (rbase + row0) * H + col) = lo0;
        *(uint32_t*)(Chi + (rbase + row0 + 8) * H + col) = h1;
        *(uint32_t*)(Clo + (rbase + row0 + 8) * H + col) = lo1;
    }
}

// ---------------------------------------------------------------------------
extern "C" void kernel_launch(void* const* d_in, const int* in_sizes, int n_in,
                              void* d_out, int out_size)
{
    const float* x  = (const float*)d_in[0];
    const float* Wq = (const float*)d_in[1];
    const float* bq = (const float*)d_in[2];
    const float* Wk = (const float*)d_in[3];
    const float* bk = (const float*)d_in[4];
    const float* Wv = (const float*)d_in[5];
    const float* bv = (const float*)d_in[6];
    const float* Wo = (const float*)d_in[7];
    const float* bo = (const float*)d_in[8];
    float* out = (float*)d_out;

    cudaFuncSetAttribute(gemm_qkv,
                         cudaFuncAttributeMaxDynamicSharedMemorySize, GEMM_SMEM);
    cudaFuncSetAttribute(gemm_o,
                         cudaFuncAttributeMaxDynamicSharedMemorySize, GEMM_SMEM);
    cudaFuncSetAttribute(attn_hmma,
                         cudaFuncAttributeMaxDynamicSharedMemorySize, ATTN_SMEM);

    __half *qh, *kh, *vhi, *vlo, *chi, *clo, *xhi, *xlo, *wthi, *wtlo;
    cudaGetSymbolAddress((void**)&qh,  g_Qh);
    cudaGetSymbolAddress((void**)&kh,  g_Kh);
    cudaGetSymbolAddress((void**)&vhi, g_Vhi);
    cudaGetSymbolAddress((void**)&vlo, g_Vlo);
    cudaGetSymbolAddress((void**)&chi, g_chi);
    cudaGetSymbolAddress((void**)&clo, g_clo);
    cudaGetSymbolAddress((void**)&xhi, g_xhi);
    cudaGetSymbolAddress((void**)&xlo, g_xlo);
    cudaGetSymbolAddress((void**)&wthi, g_WThi);
    cudaGetSymbolAddress((void**)&wtlo, g_WTlo);

    const int nelem = MTOT * H;
    const size_t WSZ = (size_t)H * H;

    split_f16_v4<<<(nelem / 4 + 255) / 256, 256>>>(x, xhi, xlo, nelem / 4);
    dim3 tgrid(H / 32, H / 32, 4), tblk(32, 8);
    transpose_split4<<<tgrid, tblk>>>(Wq, Wk, Wv, Wo, wthi, wtlo);

    dim3 qkvgrid(3 * H / 128, MTOT / 128);   // (24, 32)
    gemm_qkv<<<qkvgrid, 256, GEMM_SMEM>>>(xhi, xlo, wthi, wtlo,
        bq, bk, bv, qh, kh, vhi, vlo);

    dim3 agrid(SEQ / 64, BSZ * NH);          // (32, 32)
    attn_hmma<<<agrid, 128, ATTN_SMEM>>>(qh, kh, vhi, vlo, chi, clo);

    dim3 ogrid(H / 128, MTOT / 128);         // (8, 32)
    gemm_o<<<ogrid, 256, GEMM_SMEM>>>(chi, clo, wthi + 3 * WSZ, wtlo + 3 * WSZ,
                                      bo, out);
}